// round 1
// baseline (speedup 1.0000x reference)
#include <cuda_runtime.h>

#define N_TOTAL 557056
#define NC 64

// Scratch (device globals — no allocation allowed)
__device__ float g_m1[N_TOTAL * NC];
__device__ float g_m2[N_TOTAL * NC];
__device__ float g_hs2[N_TOTAL * NC];

__device__ __forceinline__ float4 ld4(const float* p) { return *reinterpret_cast<const float4*>(p); }
__device__ __forceinline__ void st4(float* p, float4 v) { *reinterpret_cast<float4*>(p) = v; }

// ---------------------------------------------------------------------------
// 64x64 GEMM tile machinery. 128 threads: ty = tid & 15 (row quad), tx = tid>>4
// (col octet). A tiles stored column-major in smem: As[k*64 + row].
// B (weight) stored transposed + XOR-swizzled (16B-block granularity) so both
// the staging writes and the mainloop reads are bank-conflict-free:
//   Bs[i*64 + ((((o>>2) ^ (i&15)) << 2) | (o&3))] = W[o*64 + i]
// ---------------------------------------------------------------------------

__device__ __forceinline__ void load_w(float* Bs, const float* __restrict__ W, int tid) {
#pragma unroll
    for (int r = 0; r < 32; r++) {
        int idx = r * 128 + tid;          // 0..4095
        int o = idx >> 6, i = idx & 63;
        int col = ((((o >> 2) ^ (i & 15)) << 2) | (o & 3));
        Bs[i * 64 + col] = W[idx];
    }
}

// stage 64 rows (row-major gmem, 64 floats each) into column-major smem
__device__ __forceinline__ void stage_x(float* S, const float* __restrict__ src, int tid) {
#pragma unroll
    for (int r = 0; r < 8; r++) {
        int idx = r * 128 + tid;          // 0..1023
        int row = idx >> 4, k4 = idx & 15;
        float4 v = ld4(src + row * 64 + k4 * 4);
        S[(k4 * 4 + 0) * 64 + row] = v.x;
        S[(k4 * 4 + 1) * 64 + row] = v.y;
        S[(k4 * 4 + 2) * 64 + row] = v.z;
        S[(k4 * 4 + 3) * 64 + row] = v.w;
    }
}

__device__ __forceinline__ void gemm64(const float* __restrict__ As, const float* __restrict__ Bs,
                                       float acc[4][8], int tx, int ty) {
#pragma unroll
    for (int ri = 0; ri < 4; ri++)
#pragma unroll
        for (int ci = 0; ci < 8; ci++) acc[ri][ci] = 0.f;

#pragma unroll 8
    for (int k = 0; k < 64; k++) {
        float4 a = ld4(As + k * 64 + ty * 4);
        int kb = k & 15;
        float4 b0 = ld4(Bs + k * 64 + (((tx * 2) ^ kb) << 2));
        float4 b1 = ld4(Bs + k * 64 + (((tx * 2 + 1) ^ kb) << 2));
        float av[4] = {a.x, a.y, a.z, a.w};
        float bv[8] = {b0.x, b0.y, b0.z, b0.w, b1.x, b1.y, b1.z, b1.w};
#pragma unroll
        for (int ri = 0; ri < 4; ri++)
#pragma unroll
            for (int ci = 0; ci < 8; ci++)
                acc[ri][ci] += av[ri] * bv[ci];
    }
}

// ---------------------------------------------------------------------------
// Kernel A: x -> m1 (2-layer MLP), m2 (2-layer MLP), skip (Linear) -> g_hs2
// One CTA per 64 rows.
// ---------------------------------------------------------------------------
__global__ void __launch_bounds__(128) kernelA(
    const float* __restrict__ x,
    const float* __restrict__ w_m1, const float* __restrict__ b_m1,
    const float* __restrict__ w_m2, const float* __restrict__ b_m2,
    const float* __restrict__ W_skip, const float* __restrict__ b_skip) {
    __shared__ float Xs[4096];
    __shared__ float Hs[4096];
    __shared__ float Bs[4096];
    int tid = threadIdx.x;
    int ty = tid & 15, tx = tid >> 4;
    long row0 = (long)blockIdx.x * 64;
    float acc[4][8];

    stage_x(Xs, x + row0 * 64, tid);
    load_w(Bs, w_m1, tid);
    __syncthreads();

    // ---- m1 layer 0 -> Hs ----
    gemm64(Xs, Bs, acc, tx, ty);
    __syncthreads();
#pragma unroll
    for (int ci = 0; ci < 8; ci++) {
        int col = tx * 8 + ci;
        float bb = b_m1[col];
        float4 v = make_float4(fmaxf(acc[0][ci] + bb, 0.f), fmaxf(acc[1][ci] + bb, 0.f),
                               fmaxf(acc[2][ci] + bb, 0.f), fmaxf(acc[3][ci] + bb, 0.f));
        st4(Hs + col * 64 + ty * 4, v);
    }
    load_w(Bs, w_m1 + 4096, tid);
    __syncthreads();

    // ---- m1 layer 1 -> gmem ----
    gemm64(Hs, Bs, acc, tx, ty);
#pragma unroll
    for (int ri = 0; ri < 4; ri++) {
        long row = row0 + ty * 4 + ri;
#pragma unroll
        for (int h = 0; h < 2; h++) {
            int cb = tx * 8 + h * 4;
            float4 v;
            v.x = fmaxf(acc[ri][h * 4 + 0] + b_m1[64 + cb + 0], 0.f);
            v.y = fmaxf(acc[ri][h * 4 + 1] + b_m1[64 + cb + 1], 0.f);
            v.z = fmaxf(acc[ri][h * 4 + 2] + b_m1[64 + cb + 2], 0.f);
            v.w = fmaxf(acc[ri][h * 4 + 3] + b_m1[64 + cb + 3], 0.f);
            st4(g_m1 + row * 64 + cb, v);
        }
    }
    __syncthreads();

    // ---- m2 layer 0 -> Hs ----
    load_w(Bs, w_m2, tid);
    __syncthreads();
    gemm64(Xs, Bs, acc, tx, ty);
    __syncthreads();
#pragma unroll
    for (int ci = 0; ci < 8; ci++) {
        int col = tx * 8 + ci;
        float bb = b_m2[col];
        float4 v = make_float4(fmaxf(acc[0][ci] + bb, 0.f), fmaxf(acc[1][ci] + bb, 0.f),
                               fmaxf(acc[2][ci] + bb, 0.f), fmaxf(acc[3][ci] + bb, 0.f));
        st4(Hs + col * 64 + ty * 4, v);
    }
    load_w(Bs, w_m2 + 4096, tid);
    __syncthreads();

    // ---- m2 layer 1 -> gmem ----
    gemm64(Hs, Bs, acc, tx, ty);
#pragma unroll
    for (int ri = 0; ri < 4; ri++) {
        long row = row0 + ty * 4 + ri;
#pragma unroll
        for (int h = 0; h < 2; h++) {
            int cb = tx * 8 + h * 4;
            float4 v;
            v.x = fmaxf(acc[ri][h * 4 + 0] + b_m2[64 + cb + 0], 0.f);
            v.y = fmaxf(acc[ri][h * 4 + 1] + b_m2[64 + cb + 1], 0.f);
            v.z = fmaxf(acc[ri][h * 4 + 2] + b_m2[64 + cb + 2], 0.f);
            v.w = fmaxf(acc[ri][h * 4 + 3] + b_m2[64 + cb + 3], 0.f);
            st4(g_m2 + row * 64 + cb, v);
        }
    }
    __syncthreads();

    // ---- skip (no relu) -> g_hs2 ----
    load_w(Bs, W_skip, tid);
    __syncthreads();
    gemm64(Xs, Bs, acc, tx, ty);
#pragma unroll
    for (int ri = 0; ri < 4; ri++) {
        long row = row0 + ty * 4 + ri;
#pragma unroll
        for (int h = 0; h < 2; h++) {
            int cb = tx * 8 + h * 4;
            float4 v;
            v.x = acc[ri][h * 4 + 0] + b_skip[cb + 0];
            v.y = acc[ri][h * 4 + 1] + b_skip[cb + 1];
            v.z = acc[ri][h * 4 + 2] + b_skip[cb + 2];
            v.w = acc[ri][h * 4 + 3] + b_skip[cb + 3];
            st4(g_hs2 + row * 64 + cb, v);
        }
    }
}

// ---------------------------------------------------------------------------
// Kernel B: per-graph-block, per-channel spatial matmul:
//   h[b,i,k,c] = sum_j m1[b,i,j,c] * m2[b,j,k,c];  g_hs2 += h
// Tile: 32 i x 32 k x 16 channels per CTA. 256 threads:
//   cs = t&3 (channel slot), is_ = (t>>2)&7 (i slot), ks = t>>5 (k slot)
//   thread handles 4 i x 4 k x 4 channels (c = c0 + cs + 4q) = 64 accumulators.
// smem: m1s[ii*129 + jj*16 + cc]  (pad 129 -> conflict-free a-reads)
//       m2s[jj*544 + kk*17 + cc]  (pad 17  -> conflict-free staging writes)
// ---------------------------------------------------------------------------
template <int N>
__global__ void __launch_bounds__(256) kernelB(long baseRow) {
    constexpr int TK = (N + 31) / 32;
    __shared__ float m1s[32 * 129];
    __shared__ float m2s[8 * 544];

    int t = threadIdx.x;
    int cs = t & 3, is_ = (t >> 2) & 7, ks = t >> 5;
    int b = blockIdx.x;
    int ti = blockIdx.y / TK, tk = blockIdx.y % TK;
    int c0 = blockIdx.z * 16;
    int i0 = ti * 32, k0 = tk * 32;

    long blkRow = baseRow + (long)b * N * N;
    const float* m1p = g_m1 + blkRow * 64;
    const float* m2p = g_m2 + blkRow * 64;

    float acc[4][4][4];
#pragma unroll
    for (int ri = 0; ri < 4; ri++)
#pragma unroll
        for (int rk = 0; rk < 4; rk++)
#pragma unroll
            for (int q = 0; q < 4; q++) acc[ri][rk][q] = 0.f;

    int li = t >> 3, lj = t & 7;   // m1 staging: (ii, jj)
    int mj = t >> 5, mk = t & 31;  // m2 staging: (jj, kk)

    for (int j0 = 0; j0 < N; j0 += 8) {
        __syncthreads();
        // stage m1 tile [32 i][8 j][16 c]
        {
            float4 v0, v1, v2, v3;
            int i = i0 + li;
            if (i < N) {
                const float* src = m1p + ((long)i * N + (j0 + lj)) * 64 + c0;
                v0 = ld4(src); v1 = ld4(src + 4); v2 = ld4(src + 8); v3 = ld4(src + 12);
            } else {
                v0 = v1 = v2 = v3 = make_float4(0.f, 0.f, 0.f, 0.f);
            }
            float* d = m1s + li * 129 + lj * 16;
            d[0] = v0.x;  d[1] = v0.y;  d[2] = v0.z;  d[3] = v0.w;
            d[4] = v1.x;  d[5] = v1.y;  d[6] = v1.z;  d[7] = v1.w;
            d[8] = v2.x;  d[9] = v2.y;  d[10] = v2.z; d[11] = v2.w;
            d[12] = v3.x; d[13] = v3.y; d[14] = v3.z; d[15] = v3.w;
        }
        // stage m2 tile [8 j][32 k][16 c]
        {
            float4 v0, v1, v2, v3;
            int k = k0 + mk;
            if (k < N) {
                const float* src = m2p + ((long)(j0 + mj) * N + k) * 64 + c0;
                v0 = ld4(src); v1 = ld4(src + 4); v2 = ld4(src + 8); v3 = ld4(src + 12);
            } else {
                v0 = v1 = v2 = v3 = make_float4(0.f, 0.f, 0.f, 0.f);
            }
            float* d = m2s + mj * 544 + mk * 17;
            d[0] = v0.x;  d[1] = v0.y;  d[2] = v0.z;  d[3] = v0.w;
            d[4] = v1.x;  d[5] = v1.y;  d[6] = v1.z;  d[7] = v1.w;
            d[8] = v2.x;  d[9] = v2.y;  d[10] = v2.z; d[11] = v2.w;
            d[12] = v3.x; d[13] = v3.y; d[14] = v3.z; d[15] = v3.w;
        }
        __syncthreads();

#pragma unroll
        for (int jj = 0; jj < 8; jj++) {
            float av[4][4], bv[4][4];
#pragma unroll
            for (int ri = 0; ri < 4; ri++)
#pragma unroll
                for (int q = 0; q < 4; q++)
                    av[ri][q] = m1s[(is_ * 4 + ri) * 129 + jj * 16 + cs + 4 * q];
#pragma unroll
            for (int rk = 0; rk < 4; rk++)
#pragma unroll
                for (int q = 0; q < 4; q++)
                    bv[rk][q] = m2s[jj * 544 + (ks * 4 + rk) * 17 + cs + 4 * q];
#pragma unroll
            for (int ri = 0; ri < 4; ri++)
#pragma unroll
                for (int rk = 0; rk < 4; rk++)
#pragma unroll
                    for (int q = 0; q < 4; q++)
                        acc[ri][rk][q] += av[ri][q] * bv[rk][q];
        }
    }

    // epilogue: g_hs2 (holds skip) += h
#pragma unroll
    for (int ri = 0; ri < 4; ri++) {
        int i = i0 + is_ * 4 + ri;
        if (i < N) {
#pragma unroll
            for (int rk = 0; rk < 4; rk++) {
                int k = k0 + ks * 4 + rk;
                if (k < N) {
                    float* p = g_hs2 + (blkRow + (long)i * N + k) * 64 + c0 + cs;
#pragma unroll
                    for (int q = 0; q < 4; q++)
                        p[4 * q] += acc[ri][rk][q];
                }
            }
        }
    }
}

// ---------------------------------------------------------------------------
// Kernel C: hs2 -> Linear+BN+ReLU -> Linear+BN+ReLU -> +hs2 -> out
// ---------------------------------------------------------------------------
__global__ void __launch_bounds__(128) kernelC(
    const float* __restrict__ W_u1, const float* __restrict__ b_u1,
    const float* __restrict__ g1, const float* __restrict__ beta1,
    const float* __restrict__ rm1, const float* __restrict__ rv1,
    const float* __restrict__ W_u2, const float* __restrict__ b_u2,
    const float* __restrict__ g2, const float* __restrict__ beta2,
    const float* __restrict__ rm2, const float* __restrict__ rv2,
    float* __restrict__ out) {
    __shared__ float Xs[4096];
    __shared__ float Hs[4096];
    __shared__ float Bs[4096];
    int tid = threadIdx.x;
    int ty = tid & 15, tx = tid >> 4;
    long row0 = (long)blockIdx.x * 64;
    float acc[4][8];

    stage_x(Xs, g_hs2 + row0 * 64, tid);
    load_w(Bs, W_u1, tid);
    __syncthreads();

    // layer u1: Linear + BN + ReLU -> Hs
    gemm64(Xs, Bs, acc, tx, ty);
    __syncthreads();
#pragma unroll
    for (int ci = 0; ci < 8; ci++) {
        int col = tx * 8 + ci;
        float sc = g1[col] * rsqrtf(rv1[col] + 1e-5f);
        float sh = beta1[col] - rm1[col] * sc;
        float bb = b_u1[col];
        float4 v = make_float4(fmaxf((acc[0][ci] + bb) * sc + sh, 0.f),
                               fmaxf((acc[1][ci] + bb) * sc + sh, 0.f),
                               fmaxf((acc[2][ci] + bb) * sc + sh, 0.f),
                               fmaxf((acc[3][ci] + bb) * sc + sh, 0.f));
        st4(Hs + col * 64 + ty * 4, v);
    }
    load_w(Bs, W_u2, tid);
    __syncthreads();

    // layer u2: Linear + BN + ReLU + residual(hs2) -> out
    gemm64(Hs, Bs, acc, tx, ty);
    float y[4][8];
#pragma unroll
    for (int ci = 0; ci < 8; ci++) {
        int col = tx * 8 + ci;
        float sc = g2[col] * rsqrtf(rv2[col] + 1e-5f);
        float sh = beta2[col] - rm2[col] * sc;
        float bb = b_u2[col];
        float4 xv = ld4(Xs + col * 64 + ty * 4);
        y[0][ci] = fmaxf((acc[0][ci] + bb) * sc + sh, 0.f) + xv.x;
        y[1][ci] = fmaxf((acc[1][ci] + bb) * sc + sh, 0.f) + xv.y;
        y[2][ci] = fmaxf((acc[2][ci] + bb) * sc + sh, 0.f) + xv.z;
        y[3][ci] = fmaxf((acc[3][ci] + bb) * sc + sh, 0.f) + xv.w;
    }
#pragma unroll
    for (int ri = 0; ri < 4; ri++) {
        long row = row0 + ty * 4 + ri;
#pragma unroll
        for (int h = 0; h < 2; h++) {
            int cb = tx * 8 + h * 4;
            st4(out + row * 64 + cb,
                make_float4(y[ri][h * 4 + 0], y[ri][h * 4 + 1],
                            y[ri][h * 4 + 2], y[ri][h * 4 + 3]));
        }
    }
}

// ---------------------------------------------------------------------------
extern "C" void kernel_launch(void* const* d_in, const int* in_sizes, int n_in,
                              void* d_out, int out_size) {
    (void)in_sizes; (void)n_in; (void)out_size;
    const float* x      = (const float*)d_in[0];
    const float* w_m1   = (const float*)d_in[1];
    const float* b_m1   = (const float*)d_in[2];
    const float* w_m2   = (const float*)d_in[3];
    const float* b_m2   = (const float*)d_in[4];
    const float* W_skip = (const float*)d_in[5];
    const float* b_skip = (const float*)d_in[6];
    const float* W_u1   = (const float*)d_in[7];
    const float* b_u1   = (const float*)d_in[8];
    const float* g1     = (const float*)d_in[9];
    const float* beta1  = (const float*)d_in[10];
    const float* rm1    = (const float*)d_in[11];
    const float* rv1    = (const float*)d_in[12];
    const float* W_u2   = (const float*)d_in[13];
    const float* b_u2   = (const float*)d_in[14];
    const float* g2     = (const float*)d_in[15];
    const float* beta2  = (const float*)d_in[16];
    const float* rm2    = (const float*)d_in[17];
    const float* rv2    = (const float*)d_in[18];
    float* out = (float*)d_out;

    kernelA<<<N_TOTAL / 64, 128>>>(x, w_m1, b_m1, w_m2, b_m2, W_skip, b_skip);

    // BLOCKS = [(128,32),(64,48),(32,64),(16,96)], row bases 0/131072/278528/409600
    kernelB<32><<<dim3(128, 1, 4), 256>>>(0L);
    kernelB<48><<<dim3(64, 4, 4), 256>>>(131072L);
    kernelB<64><<<dim3(32, 4, 4), 256>>>(278528L);
    kernelB<96><<<dim3(16, 9, 4), 256>>>(409600L);

    kernelC<<<N_TOTAL / 64, 128>>>(W_u1, b_u1, g1, beta1, rm1, rv1,
                                   W_u2, b_u2, g2, beta2, rm2, rv2, out);
}